// round 4
// baseline (speedup 1.0000x reference)
#include <cuda_runtime.h>
#include <math_constants.h>

// ---------------------------------------------------------------------------
// Net_40312563041045: 4-layer max-tempered MLP
//   h = 0.8 * (X @ W^T) + 0.2 * max_k(W[o,k] * x[b,k]) + b
// Shapes: B=1024, 256 -> 512 -> 512 -> 512 -> 1, fp32.
//
// R4: R3 occupancy plan with BK=32 so static smem (27.6KB) fits the 48KB cap.
// 32x64 tile, TM=2 x TN=4, 256 threads, grid=256 blocks, 2 blocks/SM.
// Packed f32x2 math (1 fma-pipe + 1 alu-pipe instr per triple).
// ---------------------------------------------------------------------------

#define BETA 0.2f
#define BM 32
#define BN 64
#define BK 32
#define TM 2
#define TN 4
#define SROW (BK + 4)   // 36 floats: 16B-aligned rows, conflict-free LDS.128

__device__ float g_h1[1024 * 512];
__device__ float g_h2[1024 * 512];

__device__ __forceinline__ unsigned smem_u32(const void* p) {
    return (unsigned)__cvta_generic_to_shared(p);
}
__device__ __forceinline__ void cp16(unsigned dst, const void* src) {
    asm volatile("cp.async.ca.shared.global [%0], [%1], 16;\n" :: "r"(dst), "l"(src));
}

// 2 triples: mul.f32x2 + add.f32x2 (fma pipe) + 2 FMNMX (alu pipe).
__device__ __forceinline__ void mt_step(unsigned long long &acc, float &mx,
                                        unsigned long long x2, unsigned long long w2) {
    asm("{\n\t"
        ".reg .b64 p;\n\t"
        ".reg .f32 plo, phi;\n\t"
        "mul.rn.f32x2 p, %2, %3;\n\t"
        "add.rn.f32x2 %0, %0, p;\n\t"
        "mov.b64 {plo, phi}, p;\n\t"
        "max.f32 %1, %1, plo;\n\t"
        "max.f32 %1, %1, phi;\n\t"
        "}" : "+l"(acc), "+f"(mx) : "l"(x2), "l"(w2));
}

template <int K>
__global__ void __launch_bounds__(256, 2)
layer_kernel(const float* __restrict__ X,   // [B, K]
             const float* __restrict__ W,   // [O, K]
             const float* __restrict__ bias,// [O]
             float* __restrict__ H,         // [B, O]
             int O)
{
    __shared__ float Xs[2][BM][SROW];   // 2*32*36*4 = 9216 B
    __shared__ float Ws[2][BN][SROW];   // 2*64*36*4 = 18432 B

    const int tid  = threadIdx.x;
    const int tcol = tid & 15;    // outputs n0 + tcol + 16*j
    const int trow = tid >> 4;    // rows m0 + trow*TM + i
    const int m0 = blockIdx.x * BM;
    const int n0 = blockIdx.y * BN;

    // staging maps: X tile 32x32 floats = 64 chunks of 16B -> threads 0..255 do
    // alternating halves; W tile 64x32 = 128 chunks.
    const int xrow = tid >> 3;        // 0..31
    const int xcol = (tid & 7) * 4;   // one 16B chunk per thread (256 = 2x coverage)
    const int wrow = tid >> 2;        // 0..63
    const int wcol = (tid & 3) * 8;   // two 16B chunks per thread

    unsigned long long acc[TM][TN];
    float mx[TM][TN];
#pragma unroll
    for (int i = 0; i < TM; i++)
#pragma unroll
        for (int j = 0; j < TN; j++) { acc[i][j] = 0ull; mx[i][j] = -CUDART_INF_F; }

    const float* Xg = X + (size_t)(m0 + xrow) * K + xcol;
    const float* Wg = W + (size_t)(n0 + wrow) * K + wcol;
    const bool do_x = (tid < 256);  // all threads stage (8 floats X-coverage via 2x map)

    const int NCH = K / BK;

    // prologue: stage chunk 0
    {
        if (tid < 256) cp16(smem_u32(&Xs[0][xrow][xcol]), Xg);
        cp16(smem_u32(&Ws[0][wrow][wcol]),     Wg);
        cp16(smem_u32(&Ws[0][wrow][wcol + 4]), Wg + 4);
        asm volatile("cp.async.commit_group;\n");
    }
    (void)do_x;

    for (int c = 0; c < NCH; ++c) {
        const int buf = c & 1;
        if (c + 1 < NCH) {
            const int nb = buf ^ 1;
            const int k0 = (c + 1) * BK;
            cp16(smem_u32(&Xs[nb][xrow][xcol]), Xg + k0);
            cp16(smem_u32(&Ws[nb][wrow][wcol]),     Wg + k0);
            cp16(smem_u32(&Ws[nb][wrow][wcol + 4]), Wg + k0 + 4);
            asm volatile("cp.async.commit_group;\n");
            asm volatile("cp.async.wait_group 1;\n");
        } else {
            asm volatile("cp.async.wait_group 0;\n");
        }
        __syncthreads();

#pragma unroll
        for (int kk = 0; kk < BK; kk += 4) {
            ulonglong2 xp[TM];
            ulonglong2 wp[TN];
#pragma unroll
            for (int i = 0; i < TM; i++)
                xp[i] = *(const ulonglong2*)&Xs[buf][trow * TM + i][kk];
#pragma unroll
            for (int j = 0; j < TN; j++)
                wp[j] = *(const ulonglong2*)&Ws[buf][tcol + 16 * j][kk];
#pragma unroll
            for (int i = 0; i < TM; i++)
#pragma unroll
                for (int j = 0; j < TN; j++) {
                    mt_step(acc[i][j], mx[i][j], xp[i].x, wp[j].x);
                    mt_step(acc[i][j], mx[i][j], xp[i].y, wp[j].y);
                }
        }
        __syncthreads();
    }

    // epilogue
#pragma unroll
    for (int i = 0; i < TM; i++) {
        const int m = m0 + trow * TM + i;
#pragma unroll
        for (int j = 0; j < TN; j++) {
            const int n = n0 + tcol + 16 * j;
            float lo = __uint_as_float((unsigned)(acc[i][j] & 0xffffffffull));
            float hi = __uint_as_float((unsigned)(acc[i][j] >> 32));
            H[(size_t)m * O + n] = (1.0f - BETA) * (lo + hi) + BETA * mx[i][j] + bias[n];
        }
    }
}

// Final layer: O = 1, K = 512. One warp per batch row, float4 vectorized.
__global__ void __launch_bounds__(256)
layer4_kernel(const float* __restrict__ X,   // [B, 512]
              const float* __restrict__ W,   // [512]
              const float* __restrict__ bias,// [1]
              float* __restrict__ out,       // [B]
              int B)
{
    const int row  = blockIdx.x * 8 + (threadIdx.x >> 5);
    const int lane = threadIdx.x & 31;
    if (row >= B) return;

    const float4* xr = (const float4*)(X + (size_t)row * 512);
    const float4* wr = (const float4*)W;

    float acc = 0.0f;
    float mx  = -CUDART_INF_F;
#pragma unroll
    for (int it = 0; it < 4; ++it) {
        float4 x = xr[lane + 32 * it];
        float4 w = wr[lane + 32 * it];
        float p0 = x.x * w.x, p1 = x.y * w.y, p2 = x.z * w.z, p3 = x.w * w.w;
        acc += (p0 + p1) + (p2 + p3);
        mx = fmaxf(fmaxf(mx, fmaxf(p0, p1)), fmaxf(p2, p3));
    }
#pragma unroll
    for (int o = 16; o > 0; o >>= 1) {
        acc += __shfl_xor_sync(0xffffffff, acc, o);
        mx = fmaxf(mx, __shfl_xor_sync(0xffffffff, mx, o));
    }
    if (lane == 0)
        out[row] = (1.0f - BETA) * acc + BETA * mx + bias[0];
}

extern "C" void kernel_launch(void* const* d_in, const int* in_sizes, int n_in,
                              void* d_out, int out_size)
{
    const float* x  = (const float*)d_in[0];
    const float* W1 = (const float*)d_in[1];
    const float* b1 = (const float*)d_in[2];
    const float* W2 = (const float*)d_in[3];
    const float* b2 = (const float*)d_in[4];
    const float* W3 = (const float*)d_in[5];
    const float* b3 = (const float*)d_in[6];
    const float* W4 = (const float*)d_in[7];
    const float* b4 = (const float*)d_in[8];
    float* out = (float*)d_out;

    const int WID = in_sizes[2];               // 512
    const int IN  = in_sizes[1] / WID;         // 256
    const int B   = in_sizes[0] / IN;          // 1024

    float* h1 = nullptr;
    float* h2 = nullptr;
    cudaGetSymbolAddress((void**)&h1, g_h1);
    cudaGetSymbolAddress((void**)&h2, g_h2);

    dim3 block(256);
    dim3 grid(B / BM, WID / BN);   // 32 x 8 = 256 blocks, all co-resident

    layer_kernel<256><<<grid, block>>>(x,  W1, b1, h1, WID);
    layer_kernel<512><<<grid, block>>>(h1, W2, b2, h2, WID);
    layer_kernel<512><<<grid, block>>>(h2, W3, b3, h1, WID);
    layer4_kernel<<<B / 8, block>>>(h1, W4, b4, out, B);
}

// round 6
// speedup vs baseline: 1.0441x; 1.0441x over previous
#include <cuda_runtime.h>
#include <math_constants.h>

// ---------------------------------------------------------------------------
// Net_40312563041045: 4-layer max-tempered MLP
//   h = 0.8 * (X @ W^T) + 0.2 * max_k(W[o,k] * x[b,k]) + b
// Shapes: B=1024, 256 -> 512 -> 512 -> 512 -> 1, fp32.
//
// R6: R2's 64x64xBK32 double-buffered tile, but 512 threads (16 warps,
// 4 warps/SMSP) with TM=4 x TN=2 to hide LDS/barrier latency at nearly the
// same instruction mix (2.19 vs 2.125 issues/triple).
// Math per 2 triples: mul.rn.f32x2 + add.rn.f32x2 (fma pipe) + 2 FMNMX (alu).
// ---------------------------------------------------------------------------

#define BETA 0.2f
#define BM 64
#define BN 64
#define BK 32
#define TM 4
#define TN 2
#define SROW (BK + 4)   // 36 floats = 144B rows: 16B-aligned, conflict-free

__device__ float g_h1[1024 * 512];
__device__ float g_h2[1024 * 512];

__device__ __forceinline__ unsigned smem_u32(const void* p) {
    return (unsigned)__cvta_generic_to_shared(p);
}
__device__ __forceinline__ void cp16(unsigned dst, const void* src) {
    asm volatile("cp.async.ca.shared.global [%0], [%1], 16;\n" :: "r"(dst), "l"(src));
}

// 2 triples: mul.f32x2 + add.f32x2 (fma pipe) + 2 FMNMX (alu pipe).
// The mov.b64 is register renaming; ptxas eliminates it.
__device__ __forceinline__ void mt_step(unsigned long long &acc, float &mx,
                                        unsigned long long x2, unsigned long long w2) {
    asm("{\n\t"
        ".reg .b64 p;\n\t"
        ".reg .f32 plo, phi;\n\t"
        "mul.rn.f32x2 p, %2, %3;\n\t"
        "add.rn.f32x2 %0, %0, p;\n\t"
        "mov.b64 {plo, phi}, p;\n\t"
        "max.f32 %1, %1, plo;\n\t"
        "max.f32 %1, %1, phi;\n\t"
        "}" : "+l"(acc), "+f"(mx) : "l"(x2), "l"(w2));
}

template <int K>
__global__ void __launch_bounds__(512, 1)
layer_kernel(const float* __restrict__ X,   // [B, K]
             const float* __restrict__ W,   // [O, K]
             const float* __restrict__ bias,// [O]
             float* __restrict__ H,         // [B, O]
             int O)
{
    __shared__ float Xs[2][BM][SROW];   // 18432 B
    __shared__ float Ws[2][BN][SROW];   // 18432 B

    const int tid  = threadIdx.x;
    const int tcol = tid & 31;    // n-group: outputs n0 + tcol + 32*j
    const int trow = tid >> 5;    // warp id = m-group: rows m0 + trow*TM + i
    const int m0 = blockIdx.x * BM;
    const int n0 = blockIdx.y * BN;

    // staging map: 512 threads x one 16B chunk each for X and for W
    const int srow = tid >> 3;       // 0..63
    const int sc   = (tid & 7) * 4;  // float col 0,4,...,28

    unsigned long long acc[TM][TN];
    float mx[TM][TN];
#pragma unroll
    for (int i = 0; i < TM; i++)
#pragma unroll
        for (int j = 0; j < TN; j++) { acc[i][j] = 0ull; mx[i][j] = -CUDART_INF_F; }

    const float* Xg = X + (size_t)(m0 + srow) * K + sc;
    const float* Wg = W + (size_t)(n0 + srow) * K + sc;

    const int NCH = K / BK;

    // prologue: stage chunk 0 into buffer 0
    cp16(smem_u32(&Xs[0][srow][sc]), Xg);
    cp16(smem_u32(&Ws[0][srow][sc]), Wg);
    asm volatile("cp.async.commit_group;\n");

    for (int c = 0; c < NCH; ++c) {
        const int buf = c & 1;
        if (c + 1 < NCH) {
            const int nb = buf ^ 1;
            const int k0 = (c + 1) * BK;
            cp16(smem_u32(&Xs[nb][srow][sc]), Xg + k0);
            cp16(smem_u32(&Ws[nb][srow][sc]), Wg + k0);
            asm volatile("cp.async.commit_group;\n");
            asm volatile("cp.async.wait_group 1;\n");
        } else {
            asm volatile("cp.async.wait_group 0;\n");
        }
        __syncthreads();

#pragma unroll
        for (int kk = 0; kk < BK; kk += 4) {
            ulonglong2 xp[TM];
            ulonglong2 wp[TN];
#pragma unroll
            for (int i = 0; i < TM; i++)
                xp[i] = *(const ulonglong2*)&Xs[buf][trow * TM + i][kk];
#pragma unroll
            for (int j = 0; j < TN; j++)
                wp[j] = *(const ulonglong2*)&Ws[buf][tcol + 32 * j][kk];
#pragma unroll
            for (int i = 0; i < TM; i++)
#pragma unroll
                for (int j = 0; j < TN; j++) {
                    mt_step(acc[i][j], mx[i][j], xp[i].x, wp[j].x);
                    mt_step(acc[i][j], mx[i][j], xp[i].y, wp[j].y);
                }
        }
        __syncthreads();
    }

    // epilogue
#pragma unroll
    for (int i = 0; i < TM; i++) {
        const int m = m0 + trow * TM + i;
#pragma unroll
        for (int j = 0; j < TN; j++) {
            const int n = n0 + tcol + 32 * j;
            float alo = __uint_as_float((unsigned)(acc[i][j] & 0xffffffffull));
            float ahi = __uint_as_float((unsigned)(acc[i][j] >> 32));
            H[(size_t)m * O + n] =
                (1.0f - BETA) * (alo + ahi) + BETA * mx[i][j] + bias[n];
        }
    }
}

// Final layer: O = 1, K = 512. One warp per batch row, float4 vectorized.
__global__ void __launch_bounds__(256)
layer4_kernel(const float* __restrict__ X,   // [B, 512]
              const float* __restrict__ W,   // [512]
              const float* __restrict__ bias,// [1]
              float* __restrict__ out,       // [B]
              int B)
{
    const int row  = blockIdx.x * 8 + (threadIdx.x >> 5);
    const int lane = threadIdx.x & 31;
    if (row >= B) return;

    const float4* xr = (const float4*)(X + (size_t)row * 512);
    const float4* wr = (const float4*)W;

    float acc = 0.0f;
    float mx  = -CUDART_INF_F;
#pragma unroll
    for (int it = 0; it < 4; ++it) {
        float4 x = xr[lane + 32 * it];
        float4 w = wr[lane + 32 * it];
        float p0 = x.x * w.x, p1 = x.y * w.y, p2 = x.z * w.z, p3 = x.w * w.w;
        acc += (p0 + p1) + (p2 + p3);
        mx = fmaxf(fmaxf(mx, fmaxf(p0, p1)), fmaxf(p2, p3));
    }
#pragma unroll
    for (int o = 16; o > 0; o >>= 1) {
        acc += __shfl_xor_sync(0xffffffff, acc, o);
        mx = fmaxf(mx, __shfl_xor_sync(0xffffffff, mx, o));
    }
    if (lane == 0)
        out[row] = (1.0f - BETA) * acc + BETA * mx + bias[0];
}

extern "C" void kernel_launch(void* const* d_in, const int* in_sizes, int n_in,
                              void* d_out, int out_size)
{
    const float* x  = (const float*)d_in[0];
    const float* W1 = (const float*)d_in[1];
    const float* b1 = (const float*)d_in[2];
    const float* W2 = (const float*)d_in[3];
    const float* b2 = (const float*)d_in[4];
    const float* W3 = (const float*)d_in[5];
    const float* b3 = (const float*)d_in[6];
    const float* W4 = (const float*)d_in[7];
    const float* b4 = (const float*)d_in[8];
    float* out = (float*)d_out;

    const int WID = in_sizes[2];               // 512
    const int IN  = in_sizes[1] / WID;         // 256
    const int B   = in_sizes[0] / IN;          // 1024

    float* h1 = nullptr;
    float* h2 = nullptr;
    cudaGetSymbolAddress((void**)&h1, g_h1);
    cudaGetSymbolAddress((void**)&h2, g_h2);

    dim3 block(512);
    dim3 grid(B / BM, WID / BN);   // 16 x 8 = 128 blocks

    layer_kernel<256><<<grid, block>>>(x,  W1, b1, h1, WID);
    layer_kernel<512><<<grid, block>>>(h1, W2, b2, h2, WID);
    layer_kernel<512><<<grid, block>>>(h2, W3, b3, h1, WID);
    layer4_kernel<<<B / 8, dim3(256)>>>(h1, W4, b4, out, B);
}